// round 7
// baseline (speedup 1.0000x reference)
#include <cuda_runtime.h>
#include <cstdint>

#define NB    16
#define NPTS  65536
#define NSEED 40
#define RAD2  0.0025f

#define FPS_CL 8
#define FPS_T  256
#define FPS_PT 32                // NPTS / (FPS_CL * FPS_T)
#define FPS_PR (FPS_PT / 2)
#define NW     (FPS_T / 32)      // 8 warps

__device__ float g_den[NB * NSEED];

// ---------------- f32x2 packed helpers (element-wise rn => bitwise == scalar)
__device__ __forceinline__ uint64_t pack2(float lo, float hi) {
    uint64_t r; asm("mov.b64 %0, {%1, %2};" : "=l"(r) : "f"(lo), "f"(hi)); return r;
}
__device__ __forceinline__ void unpack2(uint64_t v, float& lo, float& hi) {
    asm("mov.b64 {%0, %1}, %2;" : "=f"(lo), "=f"(hi) : "l"(v));
}
__device__ __forceinline__ uint64_t add2(uint64_t a, uint64_t b) {
    uint64_t r; asm("add.rn.f32x2 %0, %1, %2;" : "=l"(r) : "l"(a), "l"(b)); return r;
}
__device__ __forceinline__ uint64_t mul2(uint64_t a, uint64_t b) {
    uint64_t r; asm("mul.rn.f32x2 %0, %1, %2;" : "=l"(r) : "l"(a), "l"(b)); return r;
}
__device__ __forceinline__ uint64_t fma2(uint64_t a, uint64_t b, uint64_t c) {
    uint64_t r; asm("fma.rn.f32x2 %0, %1, %2, %3;" : "=l"(r) : "l"(a), "l"(b), "l"(c)); return r;
}

// ---------------- cluster / mbarrier helpers
__device__ __forceinline__ uint32_t ctarank() {
    uint32_t r; asm("mov.u32 %0, %%cluster_ctarank;" : "=r"(r)); return r;
}
__device__ __forceinline__ uint32_t mapa_u32(uint32_t sa, uint32_t rank) {
    uint32_t r; asm("mapa.shared::cluster.u32 %0, %1, %2;" : "=r"(r) : "r"(sa), "r"(rank));
    return r;
}
__device__ __forceinline__ void st_cluster_v4(uint32_t a, uint32_t x, uint32_t y,
                                              uint32_t z, uint32_t w) {
    asm volatile("st.shared::cluster.v4.b32 [%0], {%1,%2,%3,%4};"
                 :: "r"(a), "r"(x), "r"(y), "r"(z), "r"(w) : "memory");
}
__device__ __forceinline__ void st_cluster_b32(uint32_t a, uint32_t v) {
    asm volatile("st.shared::cluster.b32 [%0], %1;" :: "r"(a), "r"(v) : "memory");
}
__device__ __forceinline__ void mbar_init(uint32_t a, uint32_t cnt) {
    asm volatile("mbarrier.init.shared.b64 [%0], %1;" :: "r"(a), "r"(cnt) : "memory");
}
__device__ __forceinline__ void mbar_arrive_rel_cluster(uint32_t a) {
    asm volatile("mbarrier.arrive.release.cluster.shared::cluster.b64 _, [%0];"
                 :: "r"(a) : "memory");
}
__device__ __forceinline__ void mbar_wait_acq_cluster(uint32_t a, uint32_t parity) {
    asm volatile(
        "{\n\t.reg .pred P;\n\t"
        "WL_%=:\n\t"
        "mbarrier.try_wait.parity.acquire.cluster.shared::cta.b64 P, [%0], %1, 0x989680;\n\t"
        "@!P bra WL_%=;\n\t"
        "}" :: "r"(a), "r"(parity) : "memory");
}
__device__ __forceinline__ void cluster_sync_all() {
    asm volatile("barrier.cluster.arrive.aligned;" ::: "memory");
    asm volatile("barrier.cluster.wait.aligned;" ::: "memory");
}

// ---------------------------------------------------------------------------
// Kernel 1: FPS + density, fused. 8-CTA cluster per batch, 256 thr/CTA,
// 32 pts/thread register-resident. Per step (ONE __syncthreads, one DSMEM
// hop, no second barrier):
//   all warps: packed scan -> REDUX max(distbits) -> candidates rescan ->
//              REDUX min(first gi) -> lane0 STS key -> __syncthreads
//   warp0: dual-REDUX over 8 warp keys -> CTA winner {best, gi};
//          lanes 0..2 LDG winner xyz from OWN slice (L1-resident, ~40cyc);
//          lanes 0..7 st.shared::cluster {best, gi, x, y} + z to all 8 CTAs'
//          slots + mbarrier arrive (parallel)
//   every warp: mbar wait (acquire.cluster) -> dual-REDUX over the 8 slots
//          (lanes 0..7 LDS) -> winner rank -> 3x LDS broadcast of xyz ->
//          centroid in registers -> next scan. warp0 lane0 also records the
//          seed to s_seeds for the density tail.
// WAR safety (double-buffered slots b=k&1, mbar[2]): a CTA can issue its
// step-(k+2) stores into buffer b only after completing step k+1, which
// required all CTAs' step-(k+1) arrivals, each of which happens after that
// CTA's bar1 of step k+1, which orders ALL its warps' buffer-b reads from
// step k. Phase parity (k>>1)&1 matches mbar reuse every 2 steps.
// Tie-break: key {distbits<<32 | ~gi}; max => max dist then FIRST index ==
// jnp.argmax. Distance math: rn mul/add in reference order, bitexact.
// ---------------------------------------------------------------------------
__global__ void __cluster_dims__(FPS_CL, 1, 1) __launch_bounds__(FPS_T, 1)
fps_kernel(const float* __restrict__ pcs)
{
    const uint32_t rank = ctarank();
    const int batch = blockIdx.x / FPS_CL;
    const int t = threadIdx.x;
    const int lane = t & 31;
    const int warp = t >> 5;

    __shared__ __align__(8) uint64_t s_wkey[NW];
    __shared__ __align__(16) float s_seeds[NSEED][4];
    __shared__ __align__(16) uint4 s_slot4[2][FPS_CL];   // {distbits, gi, xb, yb}
    __shared__ float s_slotz[2][FPS_CL];
    __shared__ __align__(8) unsigned long long s_mbar[2];
    __shared__ float s_part[NSEED][FPS_T + 1];

    const float* base = pcs + (size_t)batch * NPTS * 3;
    const int gi0 = (int)rank * (FPS_T * FPS_PT) + t;

    // ---- load 32 points, pack pairs (2j, 2j+1)
    uint64_t PX[FPS_PR], PY[FPS_PR], PZ[FPS_PR];
#pragma unroll
    for (int j = 0; j < FPS_PR; j++) {
        const int ga = gi0 + (2 * j) * FPS_T;
        const int gb = gi0 + (2 * j + 1) * FPS_T;
        PX[j] = pack2(base[ga * 3 + 0], base[gb * 3 + 0]);
        PY[j] = pack2(base[ga * 3 + 1], base[gb * 3 + 1]);
        PZ[j] = pack2(base[ga * 3 + 2], base[gb * 3 + 2]);
    }
    unsigned db[FPS_PT];
#pragma unroll
    for (int i = 0; i < FPS_PT; i++) db[i] = __float_as_uint(1e10f);

    if (t == 0) {
        mbar_init((uint32_t)__cvta_generic_to_shared(&s_mbar[0]), FPS_CL);
        mbar_init((uint32_t)__cvta_generic_to_shared(&s_mbar[1]), FPS_CL);
    }
    if (t < 3) s_seeds[0][t] = base[t];
    if (rank == 0 && t < NSEED) g_den[batch * NSEED + t] = 0.0f;
    __syncthreads();
    cluster_sync_all();   // mbarriers initialized cluster-wide

    // per-warp register centroid (uniform across warps each step)
    float cx = s_seeds[0][0], cy = s_seeds[0][1], cz = s_seeds[0][2];

    // =================== FPS main loop ===================
#pragma unroll 1
    for (int k = 0; k < NSEED - 1; k++) {
        const int b = k & 1;
        const uint64_t ncx2 = pack2(-cx, -cx);
        const uint64_t ncy2 = pack2(-cy, -cy);
        const uint64_t ncz2 = pack2(-cz, -cz);

        // ---- packed scan, dual max accumulators
        unsigned bd0 = 0, bd1 = 0;
#pragma unroll
        for (int j = 0; j < FPS_PR; j++) {
            const uint64_t ax = add2(PX[j], ncx2);
            const uint64_t ay = add2(PY[j], ncy2);
            const uint64_t az = add2(PZ[j], ncz2);
            const uint64_t dd = add2(add2(mul2(ax, ax), mul2(ay, ay)), mul2(az, az));
            float f0, f1; unpack2(dd, f0, f1);
            db[2 * j]     = min(db[2 * j],     __float_as_uint(f0));
            db[2 * j + 1] = min(db[2 * j + 1], __float_as_uint(f1));
            bd0 = max(bd0, db[2 * j]);
            bd1 = max(bd1, db[2 * j + 1]);
        }
        const unsigned bd = max(bd0, bd1);

        // ---- warp reduce: max dist, then first (min) gi among candidates
        const unsigned wbd = __reduce_max_sync(0xffffffffu, bd);
        unsigned mygi = 0xffffffffu;
        if (bd == wbd) {
#pragma unroll
            for (int i = 0; i < FPS_PT; i++)
                if (db[i] == wbd) mygi = min(mygi, (unsigned)(gi0 + i * FPS_T));
        }
        const unsigned wgi = __reduce_min_sync(0xffffffffu, mygi);
        if (lane == 0)
            s_wkey[warp] = ((uint64_t)wbd << 32) | (unsigned)(~wgi);
        __syncthreads();                  // ---- bar1 (the only block barrier)

        // ---- warp0: CTA reduce + own-slice xyz fetch + all-to-all broadcast
        if (warp == 0) {
            const uint64_t kk = (lane < NW) ? s_wkey[lane] : 0ull;
            const unsigned khi = (unsigned)(kk >> 32);
            const unsigned klo = (unsigned)kk;
            const unsigned hi = __reduce_max_sync(0xffffffffu, khi);
            const unsigned lo = __reduce_max_sync(0xffffffffu, (khi == hi) ? klo : 0u);
            const unsigned cwidx = ~lo;

            // winner is inside this CTA's own 8192-pt slice -> L1 hit
            float v = 0.0f;
            if (lane < 3) v = base[(size_t)cwidx * 3 + lane];
            const unsigned xb = __float_as_uint(__shfl_sync(0xffffffffu, v, 0));
            const unsigned yb = __float_as_uint(__shfl_sync(0xffffffffu, v, 1));
            const unsigned zb = __float_as_uint(__shfl_sync(0xffffffffu, v, 2));

            if (lane < FPS_CL) {
                const uint32_t slot_loc =
                    (uint32_t)__cvta_generic_to_shared(&s_slot4[b][rank]);
                const uint32_t z_loc =
                    (uint32_t)__cvta_generic_to_shared(&s_slotz[b][rank]);
                const uint32_t bar_loc =
                    (uint32_t)__cvta_generic_to_shared(&s_mbar[b]);
                st_cluster_v4(mapa_u32(slot_loc, (uint32_t)lane), hi, cwidx, xb, yb);
                st_cluster_b32(mapa_u32(z_loc, (uint32_t)lane), zb);
                mbar_arrive_rel_cluster(mapa_u32(bar_loc, (uint32_t)lane));
            }
        }

        // ---- every warp: wait, reduce the 8 slots, pick winner xyz
        mbar_wait_acq_cluster((uint32_t)__cvta_generic_to_shared(&s_mbar[b]),
                              (unsigned)((k >> 1) & 1));

        unsigned shi = 0, slo = 0;
        if (lane < FPS_CL) {
            const uint4 sl = s_slot4[b][lane];
            shi = sl.x;
            slo = (unsigned)(~sl.y);
        }
        const unsigned hi2 = __reduce_max_sync(0xffffffffu, shi);
        const unsigned lo2 = __reduce_max_sync(0xffffffffu, (shi == hi2) ? slo : 0u);
        // winner rank: lanes<8 flag a match; ballot gives first matching rank
        const unsigned match =
            __ballot_sync(0xffffffffu,
                          (lane < FPS_CL) && (shi == hi2) && (slo == lo2));
        const int wr = __ffs(match) - 1;
        const uint4 ws = s_slot4[b][wr];        // same addr all lanes: broadcast
        cx = __uint_as_float(ws.z);
        cy = __uint_as_float(ws.w);
        cz = s_slotz[b][wr];
        if (warp == 0 && lane == 0) {
            s_seeds[k + 1][0] = cx; s_seeds[k + 1][1] = cy; s_seeds[k + 1][2] = cz;
        }
    }

    // =================== density tail ===================
    __syncthreads();   // s_seeds complete & slot reads done before reuse of smem
    const uint64_t signmask = 0x8000000080000000ull;
    uint64_t NPN[FPS_PR];
#pragma unroll
    for (int j = 0; j < FPS_PR; j++) {
        const uint64_t pn =
            add2(add2(mul2(PX[j], PX[j]), mul2(PY[j], PY[j])), mul2(PZ[j], PZ[j]));
        NPN[j] = pn ^ signmask;
    }

#pragma unroll 1
    for (int s = 0; s < NSEED; s++) {
        const float sx = s_seeds[s][0], sy = s_seeds[s][1], sz = s_seeds[s][2];
        const float qw = RAD2 - (sx * sx + sy * sy + sz * sz);
        const uint64_t qx2 = pack2(2.0f * sx, 2.0f * sx);
        const uint64_t qy2 = pack2(2.0f * sy, 2.0f * sy);
        const uint64_t qz2 = pack2(2.0f * sz, 2.0f * sz);
        const uint64_t qw2 = pack2(qw, qw);
        float acc = 0.0f;
#pragma unroll
        for (int j = 0; j < FPS_PR; j++) {
            uint64_t v = add2(qw2, NPN[j]);
            v = fma2(PX[j], qx2, v);
            v = fma2(PY[j], qy2, v);
            v = fma2(PZ[j], qz2, v);
            float v0, v1; unpack2(v, v0, v1);
            acc += fmaxf(v0, 0.0f);
            acc += fmaxf(v1, 0.0f);
        }
        s_part[s][t] = acc;
    }
    __syncthreads();

    if (t < NSEED) {
        const float* row = &s_part[t][0];
        float a0 = 0.f, a1 = 0.f, a2 = 0.f, a3 = 0.f;
#pragma unroll 4
        for (int i = 0; i < FPS_T; i += 4) {
            a0 += row[i]; a1 += row[i + 1]; a2 += row[i + 2]; a3 += row[i + 3];
        }
        atomicAdd(&g_den[batch * NSEED + t], (a0 + a1) + (a2 + a3));
    }
}

// ---------------------------------------------------------------------------
// Kernel 2: out = mean_b( var_{ddof=1,s}( den[b][s] ) )
// ---------------------------------------------------------------------------
__global__ void var_kernel(float* __restrict__ out)
{
    const int lane = threadIdx.x;
    float v = 0.0f;
    if (lane < NB) {
        const float* d = &g_den[lane * NSEED];
        float s = 0.0f;
        for (int i = 0; i < NSEED; i++) s += d[i];
        const float m = s * (1.0f / NSEED);
        float q = 0.0f;
        for (int i = 0; i < NSEED; i++) {
            const float e = d[i] - m;
            q += e * e;
        }
        v = q * (1.0f / (NSEED - 1));
    }
#pragma unroll
    for (int off = 8; off; off >>= 1)
        v += __shfl_down_sync(0xffffffffu, v, off);
    if (lane == 0) out[0] = v * (1.0f / NB);
}

// ---------------------------------------------------------------------------
extern "C" void kernel_launch(void* const* d_in, const int* in_sizes, int n_in,
                              void* d_out, int out_size)
{
    const float* pcs = (const float*)d_in[0];
    (void)in_sizes; (void)n_in; (void)out_size;

    fps_kernel<<<NB * FPS_CL, FPS_T>>>(pcs);
    var_kernel<<<1, 32>>>((float*)d_out);
}

// round 9
// speedup vs baseline: 1.4936x; 1.4936x over previous
#include <cuda_runtime.h>
#include <cooperative_groups.h>
#include <cstdint>

namespace cg = cooperative_groups;

#define NB    16
#define NPTS  65536
#define NSEED 40
#define RAD2  0.0025f

#define FPS_CL 8
#define FPS_T  1024
#define FPS_PT 8                 // NPTS / (FPS_CL * FPS_T)
#define FPS_PR (FPS_PT / 2)
#define NWARP  (FPS_T / 32)      // 32

__device__ float g_den[NB * NSEED];

// ---------------- f32x2 packed helpers (element-wise rn => bitwise == scalar)
__device__ __forceinline__ uint64_t pack2(float lo, float hi) {
    uint64_t r; asm("mov.b64 %0, {%1, %2};" : "=l"(r) : "f"(lo), "f"(hi)); return r;
}
__device__ __forceinline__ void unpack2(uint64_t v, float& lo, float& hi) {
    asm("mov.b64 {%0, %1}, %2;" : "=f"(lo), "=f"(hi) : "l"(v));
}
__device__ __forceinline__ uint64_t add2(uint64_t a, uint64_t b) {
    uint64_t r; asm("add.rn.f32x2 %0, %1, %2;" : "=l"(r) : "l"(a), "l"(b)); return r;
}
__device__ __forceinline__ uint64_t mul2(uint64_t a, uint64_t b) {
    uint64_t r; asm("mul.rn.f32x2 %0, %1, %2;" : "=l"(r) : "l"(a), "l"(b)); return r;
}
__device__ __forceinline__ uint64_t fma2(uint64_t a, uint64_t b, uint64_t c) {
    uint64_t r; asm("fma.rn.f32x2 %0, %1, %2, %3;" : "=l"(r) : "l"(a), "l"(b), "l"(c)); return r;
}

// ---------------- cluster / mbarrier helpers
__device__ __forceinline__ uint32_t ctarank() {
    uint32_t r; asm("mov.u32 %0, %%cluster_ctarank;" : "=r"(r)); return r;
}
__device__ __forceinline__ uint32_t mapa_u32(uint32_t sa, uint32_t rank) {
    uint32_t r; asm("mapa.shared::cluster.u32 %0, %1, %2;" : "=r"(r) : "r"(sa), "r"(rank));
    return r;
}
__device__ __forceinline__ void st_cluster_v4(uint32_t a, uint32_t x, uint32_t y,
                                              uint32_t z, uint32_t w) {
    asm volatile("st.shared::cluster.v4.b32 [%0], {%1,%2,%3,%4};"
                 :: "r"(a), "r"(x), "r"(y), "r"(z), "r"(w) : "memory");
}
__device__ __forceinline__ void st_cluster_b32(uint32_t a, uint32_t v) {
    asm volatile("st.shared::cluster.b32 [%0], %1;" :: "r"(a), "r"(v) : "memory");
}
__device__ __forceinline__ void mbar_init(uint32_t a, uint32_t cnt) {
    asm volatile("mbarrier.init.shared.b64 [%0], %1;" :: "r"(a), "r"(cnt) : "memory");
}
__device__ __forceinline__ void mbar_arrive_rel_cluster(uint32_t a) {
    asm volatile("mbarrier.arrive.release.cluster.shared::cluster.b64 _, [%0];"
                 :: "r"(a) : "memory");
}
__device__ __forceinline__ void mbar_wait_acq_cluster(uint32_t a, uint32_t parity) {
    asm volatile(
        "{\n\t.reg .pred P;\n\t"
        "WL_%=:\n\t"
        "mbarrier.try_wait.parity.acquire.cluster.shared::cta.b64 P, [%0], %1, 0x989680;\n\t"
        "@!P bra WL_%=;\n\t"
        "}" :: "r"(a), "r"(parity) : "memory");
}
__device__ __forceinline__ void cluster_sync_all() {
    asm volatile("barrier.cluster.arrive.aligned;" ::: "memory");
    asm volatile("barrier.cluster.wait.aligned;" ::: "memory");
}

// ---------------------------------------------------------------------------
// Kernel 1: FPS (R2-proven protocol) + fused density tail.
// 8-CTA cluster per batch, 1024 thr/CTA, 8 pts/thread register-resident
// (packed f32x2, element-wise rn => bitwise == reference scalar order).
// Per step: packed scan -> warp u64-key bfly reduce -> block reduce (warp0)
// -> warp0 lanes 0..7 parallel DSMEM broadcast + mbar arrive -> t==0-side
// warp0 waits once, reduces 8 slots, writes s_seeds[k+1] -> barrier.
// Tie-break: key {distbits<<32 | ~gi}, max => max dist then FIRST index
// (matches jnp.argmax). Seeds kept in per-CTA smem for the fused tail.
// Density tail: NPN precompute, 40-seed packed-FMA sweep, per-seed warp
// shfl reduce -> s_wpart[40][32] -> column sums -> global atomicAdd.
// ---------------------------------------------------------------------------
__global__ void __cluster_dims__(FPS_CL, 1, 1) __launch_bounds__(FPS_T, 1)
fps_kernel(const float* __restrict__ pcs)
{
    const uint32_t rank = ctarank();
    const int batch = blockIdx.x / FPS_CL;
    const int t = threadIdx.x;
    const int warp = t >> 5, lane = t & 31;

    __shared__ unsigned long long s_warp[NWARP];
    __shared__ unsigned s_idx;
    __shared__ float s_cand[3];
    __shared__ __align__(16) float s_seeds[NSEED][4];
    __shared__ __align__(16) uint4 s_slot4[2][FPS_CL];   // {distbits, gi, xb, yb}
    __shared__ float s_slotz[2][FPS_CL];
    __shared__ __align__(8) unsigned long long s_mbar[2];
    __shared__ float s_wpart[NSEED][NWARP];              // den partials (5 KB)

    const float* base = pcs + (size_t)batch * NPTS * 3;
    const int gi0 = (int)rank * (FPS_T * FPS_PT) + t;

    // ---- load points, pack pairs (2j, 2j+1)
    float lx[FPS_PT], ly[FPS_PT], lz[FPS_PT];
#pragma unroll
    for (int i = 0; i < FPS_PT; i++) {
        const int gi = gi0 + i * FPS_T;
        lx[i] = base[gi * 3 + 0];
        ly[i] = base[gi * 3 + 1];
        lz[i] = base[gi * 3 + 2];
    }
    uint64_t PX[FPS_PR], PY[FPS_PR], PZ[FPS_PR];
    float dist[FPS_PT];
#pragma unroll
    for (int j = 0; j < FPS_PR; j++) {
        PX[j] = pack2(lx[2 * j], lx[2 * j + 1]);
        PY[j] = pack2(ly[2 * j], ly[2 * j + 1]);
        PZ[j] = pack2(lz[2 * j], lz[2 * j + 1]);
    }
#pragma unroll
    for (int i = 0; i < FPS_PT; i++) dist[i] = 1e10f;

    if (t == 0) {
        mbar_init((uint32_t)__cvta_generic_to_shared(&s_mbar[0]), FPS_CL);
        mbar_init((uint32_t)__cvta_generic_to_shared(&s_mbar[1]), FPS_CL);
        s_seeds[0][0] = base[0]; s_seeds[0][1] = base[1]; s_seeds[0][2] = base[2];
    }
    if (rank == 0 && t < NSEED) g_den[batch * NSEED + t] = 0.0f;
    __syncthreads();
    cluster_sync_all();   // all mbarriers initialized cluster-wide

    // =================== FPS main loop (R2 protocol) ===================
#pragma unroll 1
    for (int k = 0; k < NSEED - 1; k++) {
        const float cx = s_seeds[k][0], cy = s_seeds[k][1], cz = s_seeds[k][2];
        const uint64_t ncx2 = pack2(-cx, -cx);
        const uint64_t ncy2 = pack2(-cy, -cy);
        const uint64_t ncz2 = pack2(-cz, -cz);

        // ---- packed scan: d = ((dx*dx + dy*dy) + dz*dz), exact rn order
        float bd = -1.0f;
#pragma unroll
        for (int j = 0; j < FPS_PR; j++) {
            const uint64_t dx2 = add2(PX[j], ncx2);
            const uint64_t dy2 = add2(PY[j], ncy2);
            const uint64_t dz2 = add2(PZ[j], ncz2);
            const uint64_t dd =
                add2(add2(mul2(dx2, dx2), mul2(dy2, dy2)), mul2(dz2, dz2));
            float d0, d1; unpack2(dd, d0, d1);
            dist[2 * j]     = fminf(dist[2 * j],     d0);
            dist[2 * j + 1] = fminf(dist[2 * j + 1], d1);
            bd = fmaxf(bd, dist[2 * j]);
            bd = fmaxf(bd, dist[2 * j + 1]);
        }

        // ---- warp bfly max
#pragma unroll
        for (int off = 16; off; off >>= 1)
            bd = fmaxf(bd, __shfl_xor_sync(0xffffffffu, bd, off));
        if (lane == 0) s_warp[warp] = __float_as_uint(bd);
        if (t == 0) s_idx = 0xffffffffu;
        __syncthreads();

        // ---- block max (every warp reduces the 32 warp maxima)
        float ctabd = __uint_as_float((unsigned)s_warp[lane]);
#pragma unroll
        for (int off = 16; off; off >>= 1)
            ctabd = fmaxf(ctabd, __shfl_xor_sync(0xffffffffu, ctabd, off));

        // ---- rare candidate warps: first index (min gi) via smem atomicMin
        if (bd == ctabd) {
            unsigned mygi = 0xffffffffu;
#pragma unroll
            for (int i = 0; i < FPS_PT; i++)
                if (dist[i] == ctabd) mygi = min(mygi, (unsigned)(gi0 + i * FPS_T));
            atomicMin(&s_idx, mygi);
        }
        __syncthreads();

        const unsigned widx = s_idx;
        if (bd == ctabd) {
#pragma unroll
            for (int i = 0; i < FPS_PT; i++) {
                if ((unsigned)(gi0 + i * FPS_T) == widx) {
                    float x0, x1, y0, y1, z0, z1;
                    unpack2(PX[i >> 1], x0, x1);
                    unpack2(PY[i >> 1], y0, y1);
                    unpack2(PZ[i >> 1], z0, z1);
                    s_cand[0] = (i & 1) ? x1 : x0;
                    s_cand[1] = (i & 1) ? y1 : y0;
                    s_cand[2] = (i & 1) ? z1 : z0;
                }
            }
        }
        __syncthreads();

        // ---- cross-CTA exchange (warp0 only), double-buffered slots+mbarrier
        const int b = k & 1;
        if (warp == 0) {
            if (lane < FPS_CL) {
                const unsigned db = __float_as_uint(ctabd);
                const unsigned xb = __float_as_uint(s_cand[0]);
                const unsigned yb = __float_as_uint(s_cand[1]);
                const unsigned zb = __float_as_uint(s_cand[2]);
                const uint32_t slot_loc =
                    (uint32_t)__cvta_generic_to_shared(&s_slot4[b][rank]);
                const uint32_t zloc =
                    (uint32_t)__cvta_generic_to_shared(&s_slotz[b][rank]);
                const uint32_t barloc =
                    (uint32_t)__cvta_generic_to_shared(&s_mbar[b]);
                const uint32_t slot_rem = mapa_u32(slot_loc, (uint32_t)lane);
                const uint32_t z_rem    = mapa_u32(zloc,    (uint32_t)lane);
                const uint32_t bar_rem  = mapa_u32(barloc,  (uint32_t)lane);
                st_cluster_v4(slot_rem, db, widx, xb, yb);
                st_cluster_b32(z_rem, zb);
                mbar_arrive_rel_cluster(bar_rem);
            }
            mbar_wait_acq_cluster((uint32_t)__cvta_generic_to_shared(&s_mbar[b]),
                                  (unsigned)((k >> 1) & 1));

            const int l = lane & (FPS_CL - 1);
            const uint4 sl = s_slot4[b][l];
            const float slz = s_slotz[b][l];
            unsigned long long key =
                ((unsigned long long)sl.x << 32) | (unsigned)(~sl.y);
            const unsigned long long mykey = key;
#pragma unroll
            for (int off = 4; off; off >>= 1) {
                unsigned long long ok = __shfl_xor_sync(0xffffffffu, key, off);
                if (ok > key) key = ok;
            }
            const unsigned mask =
                __ballot_sync(0xffffffffu, mykey == key) & ((1u << FPS_CL) - 1u);
            const int src = __ffs(mask) - 1;
            const float wx = __shfl_sync(0xffffffffu, __uint_as_float(sl.z), src);
            const float wy = __shfl_sync(0xffffffffu, __uint_as_float(sl.w), src);
            const float wz = __shfl_sync(0xffffffffu, slz, src);
            if (lane == 0) {
                s_seeds[k + 1][0] = wx;
                s_seeds[k + 1][1] = wy;
                s_seeds[k + 1][2] = wz;
            }
        }
        __syncthreads();
    }

    // =================== fused density tail ===================
    // NPN[j] = -((x*x + y*y) + z*z) per packed pair
    const uint64_t signmask = 0x8000000080000000ull;
    uint64_t NPN[FPS_PR];
#pragma unroll
    for (int j = 0; j < FPS_PR; j++) {
        const uint64_t pn =
            add2(add2(mul2(PX[j], PX[j]), mul2(PY[j], PY[j])), mul2(PZ[j], PZ[j]));
        NPN[j] = pn ^ signmask;
    }

#pragma unroll 1
    for (int s = 0; s < NSEED; s++) {
        const float sx = s_seeds[s][0], sy = s_seeds[s][1], sz = s_seeds[s][2];
        const float qw = RAD2 - (sx * sx + sy * sy + sz * sz);
        const uint64_t qx2 = pack2(2.0f * sx, 2.0f * sx);
        const uint64_t qy2 = pack2(2.0f * sy, 2.0f * sy);
        const uint64_t qz2 = pack2(2.0f * sz, 2.0f * sz);
        const uint64_t qw2 = pack2(qw, qw);
        float acc = 0.0f;
#pragma unroll
        for (int j = 0; j < FPS_PR; j++) {
            uint64_t v = add2(qw2, NPN[j]);
            v = fma2(PX[j], qx2, v);
            v = fma2(PY[j], qy2, v);
            v = fma2(PZ[j], qz2, v);
            float v0, v1; unpack2(v, v0, v1);
            acc += fmaxf(v0, 0.0f);
            acc += fmaxf(v1, 0.0f);
        }
        // warp reduce
#pragma unroll
        for (int off = 16; off; off >>= 1)
            acc += __shfl_xor_sync(0xffffffffu, acc, off);
        if (lane == 0) s_wpart[s][warp] = acc;
    }
    __syncthreads();

    if (t < NSEED) {
        const float* row = &s_wpart[t][0];
        float a0 = 0.f, a1 = 0.f, a2 = 0.f, a3 = 0.f;
#pragma unroll
        for (int i = 0; i < NWARP; i += 4) {
            a0 += row[i]; a1 += row[i + 1]; a2 += row[i + 2]; a3 += row[i + 3];
        }
        atomicAdd(&g_den[batch * NSEED + t], (a0 + a1) + (a2 + a3));
    }
}

// ---------------------------------------------------------------------------
// Kernel 2: out = mean_b( var_{ddof=1,s}( den[b][s] ) )
// ---------------------------------------------------------------------------
__global__ void var_kernel(float* __restrict__ out)
{
    const int lane = threadIdx.x;
    float v = 0.0f;
    if (lane < NB) {
        const float* d = &g_den[lane * NSEED];
        float s = 0.0f;
        for (int i = 0; i < NSEED; i++) s += d[i];
        const float m = s * (1.0f / NSEED);
        float q = 0.0f;
        for (int i = 0; i < NSEED; i++) {
            const float e = d[i] - m;
            q += e * e;
        }
        v = q * (1.0f / (NSEED - 1));
    }
#pragma unroll
    for (int off = 8; off; off >>= 1)
        v += __shfl_down_sync(0xffffffffu, v, off);
    if (lane == 0) out[0] = v * (1.0f / NB);
}

// ---------------------------------------------------------------------------
extern "C" void kernel_launch(void* const* d_in, const int* in_sizes, int n_in,
                              void* d_out, int out_size)
{
    const float* pcs = (const float*)d_in[0];
    (void)in_sizes; (void)n_in; (void)out_size;

    fps_kernel<<<NB * FPS_CL, FPS_T>>>(pcs);
    var_kernel<<<1, 32>>>((float*)d_out);
}

// round 10
// speedup vs baseline: 1.6499x; 1.1046x over previous
#include <cuda_runtime.h>
#include <cooperative_groups.h>
#include <cstdint>

namespace cg = cooperative_groups;

#define NB    16
#define NPTS  65536
#define NSEED 40
#define RAD2  0.0025f

#define FPS_CL 8
#define FPS_T  1024
#define FPS_PT 8                 // NPTS / (FPS_CL * FPS_T)
#define FPS_PR (FPS_PT / 2)

#define DEN_T      256
#define DEN_PT     8             // consecutive points per thread
#define DEN_PRR    (DEN_PT / 2)
#define DEN_CHUNKS (NPTS / (DEN_T * DEN_PT))   // 32

__device__ float g_seeds[NB * NSEED * 3];
__device__ float g_den[NB * NSEED];

// ---------------- f32x2 packed helpers (element-wise rn => bitwise == scalar)
__device__ __forceinline__ uint64_t pack2(float lo, float hi) {
    uint64_t r; asm("mov.b64 %0, {%1, %2};" : "=l"(r) : "f"(lo), "f"(hi)); return r;
}
__device__ __forceinline__ void unpack2(uint64_t v, float& lo, float& hi) {
    asm("mov.b64 {%0, %1}, %2;" : "=f"(lo), "=f"(hi) : "l"(v));
}
__device__ __forceinline__ uint64_t add2(uint64_t a, uint64_t b) {
    uint64_t r; asm("add.rn.f32x2 %0, %1, %2;" : "=l"(r) : "l"(a), "l"(b)); return r;
}
__device__ __forceinline__ uint64_t mul2(uint64_t a, uint64_t b) {
    uint64_t r; asm("mul.rn.f32x2 %0, %1, %2;" : "=l"(r) : "l"(a), "l"(b)); return r;
}
__device__ __forceinline__ uint64_t fma2(uint64_t a, uint64_t b, uint64_t c) {
    uint64_t r; asm("fma.rn.f32x2 %0, %1, %2, %3;" : "=l"(r) : "l"(a), "l"(b), "l"(c)); return r;
}

// ---------------- cluster / mbarrier helpers
__device__ __forceinline__ uint32_t ctarank() {
    uint32_t r; asm("mov.u32 %0, %%cluster_ctarank;" : "=r"(r)); return r;
}
__device__ __forceinline__ uint32_t mapa_u32(uint32_t sa, uint32_t rank) {
    uint32_t r; asm("mapa.shared::cluster.u32 %0, %1, %2;" : "=r"(r) : "r"(sa), "r"(rank));
    return r;
}
__device__ __forceinline__ void st_cluster_v4(uint32_t a, uint32_t x, uint32_t y,
                                              uint32_t z, uint32_t w) {
    asm volatile("st.shared::cluster.v4.b32 [%0], {%1,%2,%3,%4};"
                 :: "r"(a), "r"(x), "r"(y), "r"(z), "r"(w) : "memory");
}
__device__ __forceinline__ void st_cluster_b32(uint32_t a, uint32_t v) {
    asm volatile("st.shared::cluster.b32 [%0], %1;" :: "r"(a), "r"(v) : "memory");
}
__device__ __forceinline__ void mbar_init(uint32_t a, uint32_t cnt) {
    asm volatile("mbarrier.init.shared.b64 [%0], %1;" :: "r"(a), "r"(cnt) : "memory");
}
__device__ __forceinline__ void mbar_arrive_rel_cluster(uint32_t a) {
    asm volatile("mbarrier.arrive.release.cluster.shared::cluster.b64 _, [%0];"
                 :: "r"(a) : "memory");
}
__device__ __forceinline__ void mbar_wait_acq_cluster(uint32_t a, uint32_t parity) {
    asm volatile(
        "{\n\t.reg .pred P;\n\t"
        "WL_%=:\n\t"
        "mbarrier.try_wait.parity.acquire.cluster.shared::cta.b64 P, [%0], %1, 0x989680;\n\t"
        "@!P bra WL_%=;\n\t"
        "}" :: "r"(a), "r"(parity) : "memory");
}
__device__ __forceinline__ void cluster_sync_all() {
    asm volatile("barrier.cluster.arrive.aligned;" ::: "memory");
    asm volatile("barrier.cluster.wait.aligned;" ::: "memory");
}

// ---------------------------------------------------------------------------
// Kernel 1: farthest point sampling — VERBATIM the best-measured (R2, 103us)
// protocol. 8-CTA cluster per batch, 1024 thr/CTA, 8 pts/thread register-
// resident packed f32x2 (element-wise rn => bitwise == reference order).
// Tie-break: u64 key (distbits<<32)|~gi, max => first index == jnp.argmax.
// ---------------------------------------------------------------------------
__global__ void __cluster_dims__(FPS_CL, 1, 1) __launch_bounds__(FPS_T, 1)
fps_kernel(const float* __restrict__ pcs)
{
    const uint32_t rank = ctarank();
    const int batch = blockIdx.x / FPS_CL;
    const int t = threadIdx.x;
    const int warp = t >> 5, lane = t & 31;

    __shared__ float s_warp[32];
    __shared__ unsigned s_idx;
    __shared__ float s_cand[3];
    __shared__ float s_cent[3];
    __shared__ __align__(16) uint4 s_slot4[2][FPS_CL];   // {distbits, gi, xbits, ybits}
    __shared__ float s_slotz[2][FPS_CL];
    __shared__ __align__(8) unsigned long long s_mbar[2];

    const float* base = pcs + (size_t)batch * NPTS * 3;
    const int gi0 = (int)rank * (FPS_T * FPS_PT) + t;

    // load points, pack pairs (2j, 2j+1)
    float lx[FPS_PT], ly[FPS_PT], lz[FPS_PT];
#pragma unroll
    for (int i = 0; i < FPS_PT; i++) {
        const int gi = gi0 + i * FPS_T;
        lx[i] = base[gi * 3 + 0];
        ly[i] = base[gi * 3 + 1];
        lz[i] = base[gi * 3 + 2];
    }
    uint64_t PX[FPS_PR], PY[FPS_PR], PZ[FPS_PR];
    float dist[FPS_PT];
#pragma unroll
    for (int j = 0; j < FPS_PR; j++) {
        PX[j] = pack2(lx[2 * j], lx[2 * j + 1]);
        PY[j] = pack2(ly[2 * j], ly[2 * j + 1]);
        PZ[j] = pack2(lz[2 * j], lz[2 * j + 1]);
    }
#pragma unroll
    for (int i = 0; i < FPS_PT; i++) dist[i] = 1e10f;

    if (t == 0) {
        mbar_init((uint32_t)__cvta_generic_to_shared(&s_mbar[0]), FPS_CL);
        mbar_init((uint32_t)__cvta_generic_to_shared(&s_mbar[1]), FPS_CL);
        s_cent[0] = base[0]; s_cent[1] = base[1]; s_cent[2] = base[2];
    }
    if (rank == 0) {
        if (t < NSEED) g_den[batch * NSEED + t] = 0.0f;
        if (t == 0) {
            g_seeds[(batch * NSEED) * 3 + 0] = base[0];
            g_seeds[(batch * NSEED) * 3 + 1] = base[1];
            g_seeds[(batch * NSEED) * 3 + 2] = base[2];
        }
    }
    __syncthreads();
    cluster_sync_all();   // all mbarriers initialized cluster-wide

#pragma unroll 1
    for (int k = 0; k < NSEED - 1; k++) {
        const float cx = s_cent[0], cy = s_cent[1], cz = s_cent[2];
        const uint64_t ncx2 = pack2(-cx, -cx);
        const uint64_t ncy2 = pack2(-cy, -cy);
        const uint64_t ncz2 = pack2(-cz, -cz);

        // ---- packed scan: d = ((dx*dx + dy*dy) + dz*dz), exact rn order
        float bd = -1.0f;
#pragma unroll
        for (int j = 0; j < FPS_PR; j++) {
            const uint64_t dx2 = add2(PX[j], ncx2);
            const uint64_t dy2 = add2(PY[j], ncy2);
            const uint64_t dz2 = add2(PZ[j], ncz2);
            const uint64_t dd =
                add2(add2(mul2(dx2, dx2), mul2(dy2, dy2)), mul2(dz2, dz2));
            float d0, d1; unpack2(dd, d0, d1);
            dist[2 * j]     = fminf(dist[2 * j],     d0);
            dist[2 * j + 1] = fminf(dist[2 * j + 1], d1);
            bd = fmaxf(bd, dist[2 * j]);
            bd = fmaxf(bd, dist[2 * j + 1]);
        }

        // ---- warp bfly max
#pragma unroll
        for (int off = 16; off; off >>= 1)
            bd = fmaxf(bd, __shfl_xor_sync(0xffffffffu, bd, off));
        if (lane == 0) s_warp[warp] = bd;
        if (t == 0) s_idx = 0xffffffffu;
        __syncthreads();

        // ---- block max (every warp reduces the 32 warp maxima)
        float ctabd = s_warp[lane];
#pragma unroll
        for (int off = 16; off; off >>= 1)
            ctabd = fmaxf(ctabd, __shfl_xor_sync(0xffffffffu, ctabd, off));

        // ---- rare candidate warps: first index (min gi) via smem atomicMin
        if (bd == ctabd) {
            unsigned mygi = 0xffffffffu;
#pragma unroll
            for (int i = 0; i < FPS_PT; i++)
                if (dist[i] == ctabd) mygi = min(mygi, (unsigned)(gi0 + i * FPS_T));
            atomicMin(&s_idx, mygi);
        }
        __syncthreads();

        const unsigned widx = s_idx;
        if (bd == ctabd) {
#pragma unroll
            for (int i = 0; i < FPS_PT; i++) {
                if ((unsigned)(gi0 + i * FPS_T) == widx) {
                    float x0, x1, y0, y1, z0, z1;
                    unpack2(PX[i >> 1], x0, x1);
                    unpack2(PY[i >> 1], y0, y1);
                    unpack2(PZ[i >> 1], z0, z1);
                    s_cand[0] = (i & 1) ? x1 : x0;
                    s_cand[1] = (i & 1) ? y1 : y0;
                    s_cand[2] = (i & 1) ? z1 : z0;
                }
            }
        }
        __syncthreads();

        // ---- cross-CTA exchange (warp0 only), double-buffered slots+mbarrier
        const int b = k & 1;
        if (warp == 0) {
            if (lane < FPS_CL) {
                const unsigned db = __float_as_uint(ctabd);
                const unsigned xb = __float_as_uint(s_cand[0]);
                const unsigned yb = __float_as_uint(s_cand[1]);
                const unsigned zb = __float_as_uint(s_cand[2]);
                const uint32_t slot_loc =
                    (uint32_t)__cvta_generic_to_shared(&s_slot4[b][rank]);
                const uint32_t zloc =
                    (uint32_t)__cvta_generic_to_shared(&s_slotz[b][rank]);
                const uint32_t barloc =
                    (uint32_t)__cvta_generic_to_shared(&s_mbar[b]);
                const uint32_t slot_rem = mapa_u32(slot_loc, (uint32_t)lane);
                const uint32_t z_rem    = mapa_u32(zloc,    (uint32_t)lane);
                const uint32_t bar_rem  = mapa_u32(barloc,  (uint32_t)lane);
                st_cluster_v4(slot_rem, db, widx, xb, yb);
                st_cluster_b32(z_rem, zb);
                mbar_arrive_rel_cluster(bar_rem);
            }
            mbar_wait_acq_cluster((uint32_t)__cvta_generic_to_shared(&s_mbar[b]),
                                  (unsigned)((k >> 1) & 1));

            const int l = lane & (FPS_CL - 1);
            const uint4 sl = s_slot4[b][l];
            const float slz = s_slotz[b][l];
            unsigned long long key =
                ((unsigned long long)sl.x << 32) | (unsigned)(~sl.y);
            const unsigned long long mykey = key;
#pragma unroll
            for (int off = 4; off; off >>= 1) {
                unsigned long long ok = __shfl_xor_sync(0xffffffffu, key, off);
                if (ok > key) key = ok;
            }
            const unsigned mask =
                __ballot_sync(0xffffffffu, mykey == key) & ((1u << FPS_CL) - 1u);
            const int src = __ffs(mask) - 1;
            const float wx = __shfl_sync(0xffffffffu, __uint_as_float(sl.z), src);
            const float wy = __shfl_sync(0xffffffffu, __uint_as_float(sl.w), src);
            const float wz = __shfl_sync(0xffffffffu, slz, src);
            if (lane == 0) { s_cent[0] = wx; s_cent[1] = wy; s_cent[2] = wz; }
            if (rank == 0 && lane == 1) {
                float* gs = &g_seeds[(batch * NSEED + k + 1) * 3];
                gs[0] = wx; gs[1] = wy; gs[2] = wz;
            }
        }
        __syncthreads();
    }
    cluster_sync_all();
}

// ---------------------------------------------------------------------------
// Kernel 2: den[b][s] = sum_n relu(r^2 - (|s|^2 + |p|^2 - 2 s.p))
// Each thread: 8 CONSECUTIVE points via 6x LDG.128 (16B-aligned since
// p0*12B with p0 % 8 == 0), packed f32x2 pairs, 40-seed FMA sweep,
// sparse predicated atomicAdd.
// ---------------------------------------------------------------------------
__global__ void __launch_bounds__(DEN_T)
den_kernel(const float* __restrict__ pcs)
{
    const int batch = blockIdx.y;
    const int chunk = blockIdx.x;
    const int t = threadIdx.x;

    __shared__ float4 ss[NSEED];
    if (t < NSEED) {
        const float* gs = &g_seeds[(batch * NSEED + t) * 3];
        const float sx = gs[0], sy = gs[1], sz = gs[2];
        const float sn = sx * sx + sy * sy + sz * sz;
        ss[t] = make_float4(2.0f * sx, 2.0f * sy, 2.0f * sz, RAD2 - sn);
    }
    __syncthreads();

    const float* base = pcs + (size_t)batch * NPTS * 3;
    const int p0 = (chunk * DEN_T + t) * DEN_PT;     // 8 consecutive points

    // 6 x float4 = 24 floats = 8 points (vectorized, aligned)
    const float4* fp = reinterpret_cast<const float4*>(base + (size_t)p0 * 3);
    float f[DEN_PT * 3];
#pragma unroll
    for (int i = 0; i < (DEN_PT * 3) / 4; i++) {
        const float4 v = __ldg(&fp[i]);
        f[4 * i + 0] = v.x; f[4 * i + 1] = v.y;
        f[4 * i + 2] = v.z; f[4 * i + 3] = v.w;
    }

    uint64_t X2[DEN_PRR], Y2[DEN_PRR], Z2[DEN_PRR], NPN2[DEN_PRR];
#pragma unroll
    for (int j = 0; j < DEN_PRR; j++) {
        const float x0 = f[6 * j + 0], y0 = f[6 * j + 1], z0 = f[6 * j + 2];
        const float x1 = f[6 * j + 3], y1 = f[6 * j + 4], z1 = f[6 * j + 5];
        X2[j] = pack2(x0, x1);
        Y2[j] = pack2(y0, y1);
        Z2[j] = pack2(z0, z1);
        const float pn0 = fmaf(z0, z0, fmaf(y0, y0, x0 * x0));
        const float pn1 = fmaf(z1, z1, fmaf(y1, y1, x1 * x1));
        NPN2[j] = pack2(-pn0, -pn1);
    }

#pragma unroll 2
    for (int s = 0; s < NSEED; s++) {
        const float4 q = ss[s];
        const uint64_t qx2 = pack2(q.x, q.x);
        const uint64_t qy2 = pack2(q.y, q.y);
        const uint64_t qz2 = pack2(q.z, q.z);
        const uint64_t qw2 = pack2(q.w, q.w);
        float acc = 0.0f;
#pragma unroll
        for (int j = 0; j < DEN_PRR; j++) {
            uint64_t v = add2(qw2, NPN2[j]);
            v = fma2(X2[j], qx2, v);
            v = fma2(Y2[j], qy2, v);
            v = fma2(Z2[j], qz2, v);
            float v0, v1; unpack2(v, v0, v1);
            acc += fmaxf(v0, 0.0f);
            acc += fmaxf(v1, 0.0f);
        }
        if (acc != 0.0f) atomicAdd(&g_den[batch * NSEED + s], acc);
    }
}

// ---------------------------------------------------------------------------
// Kernel 3: out = mean_b( var_{ddof=1,s}( den[b][s] ) )
// ---------------------------------------------------------------------------
__global__ void var_kernel(float* __restrict__ out)
{
    const int lane = threadIdx.x;
    float v = 0.0f;
    if (lane < NB) {
        const float* d = &g_den[lane * NSEED];
        float s = 0.0f;
        for (int i = 0; i < NSEED; i++) s += d[i];
        const float m = s * (1.0f / NSEED);
        float q = 0.0f;
        for (int i = 0; i < NSEED; i++) {
            const float e = d[i] - m;
            q += e * e;
        }
        v = q * (1.0f / (NSEED - 1));
    }
#pragma unroll
    for (int off = 8; off; off >>= 1)
        v += __shfl_down_sync(0xffffffffu, v, off);
    if (lane == 0) out[0] = v * (1.0f / NB);
}

// ---------------------------------------------------------------------------
extern "C" void kernel_launch(void* const* d_in, const int* in_sizes, int n_in,
                              void* d_out, int out_size)
{
    const float* pcs = (const float*)d_in[0];
    (void)in_sizes; (void)n_in; (void)out_size;

    fps_kernel<<<NB * FPS_CL, FPS_T>>>(pcs);
    den_kernel<<<dim3(DEN_CHUNKS, NB), DEN_T>>>(pcs);
    var_kernel<<<1, 32>>>((float*)d_out);
}